// round 15
// baseline (speedup 1.0000x reference)
#include <cuda_runtime.h>
#include <cuda_fp16.h>
#include <cstdint>

// G=1024 groups (1 CTA each), K=16 agents, T=32, D=64.
// out[n,t,0:64]=group mean of h ; out[n,t,64:128]=h ; h=fc2(relu(LN(fc1(x))))
// mma.sync m16n8k16 fp16 single-term; warp-private smem staging for coalesced
// x loads and h stores; fused register-resident mean broadcast epilogue.
// R15: software-pipelined x loads with double-buffered A stage — tile mt+1's
// LDGs issue before GEMM1 of tile mt and are staged after GEMM2.
#define GRPS 1024

// smem byte offsets
#define OFF_W1  0          // 64 rows x 128B fp16, swizzled
#define OFF_W2  8192
#define OFF_AST 16384      // A stage: 2 bufs x 8 warps x 16 rows x 128B = 32KB
#define OFF_HST 49152      // h stage: 8 warps x 16 rows x 256B f32 = 32KB
#define OFF_B1  81920
#define OFF_B2  82176
#define OFF_LNW 82432
#define OFF_LNB 82688
#define SMEM_TOTAL 82944
// post-loop alias:
#define OFF_RED   OFF_HST  // [128 rows][64 cols] f32, 256B rows, chunk-swizzled
#define ABUF 16384         // A-stage buffer stride

__device__ __forceinline__ uint32_t smem_u32(const void* p) {
    uint32_t a;
    asm("{ .reg .u64 t; cvta.to.shared.u64 t, %1; cvt.u32.u64 %0, t; }" : "=r"(a) : "l"(p));
    return a;
}
__device__ __forceinline__ void ldmx4(uint32_t addr, uint32_t* r) {
    asm volatile("ldmatrix.sync.aligned.m8n8.x4.shared.b16 {%0,%1,%2,%3}, [%4];"
                 : "=r"(r[0]), "=r"(r[1]), "=r"(r[2]), "=r"(r[3]) : "r"(addr));
}
__device__ __forceinline__ void mma_f16(float* c, const uint32_t* a,
                                        uint32_t b0, uint32_t b1) {
    asm volatile(
        "mma.sync.aligned.m16n8k16.row.col.f32.f16.f16.f32 "
        "{%0,%1,%2,%3}, {%4,%5,%6,%7}, {%8,%9}, {%0,%1,%2,%3};"
        : "+f"(c[0]), "+f"(c[1]), "+f"(c[2]), "+f"(c[3])
        : "r"(a[0]), "r"(a[1]), "r"(a[2]), "r"(a[3]), "r"(b0), "r"(b1));
}
__device__ __forceinline__ uint32_t cvt2(float x0, float x1) {
    __half2 h = __floats2half2_rn(x0, x1);
    return *(uint32_t*)&h;
}
__device__ __forceinline__ void stcs4(float* p, float4 v) {
    asm volatile("st.global.cs.v4.f32 [%0], {%1,%2,%3,%4};"
                 :: "l"(p), "f"(v.x), "f"(v.y), "f"(v.z), "f"(v.w) : "memory");
}
// convert 8 consecutive fp32 -> one 16B fp16 chunk, swizzled store (weights)
__device__ __forceinline__ void conv_store8(char* sm, int off, int row, int ch,
                                            float4 a, float4 b) {
    uint4 v;
    v.x = cvt2(a.x, a.y); v.y = cvt2(a.z, a.w);
    v.z = cvt2(b.x, b.y); v.w = cvt2(b.z, b.w);
    int bo = row * 128 + ((ch ^ (row & 7)) << 4);
    *(uint4*)(sm + off + bo) = v;
}

// 16x64 stripe GEMM vs 64x64 fp16 weights, register A (single term).
__device__ __forceinline__ void gemm64r(const uint32_t ah[4][4],
                                        uint32_t wB,
                                        uint32_t lhalf, uint32_t lxor,
                                        float c[8][4]) {
    #pragma unroll
    for (int kk = 0; kk < 4; kk++) {
        uint32_t co = ((((uint32_t)(kk << 1) + lhalf) ^ lxor) << 4);
        #pragma unroll
        for (int np = 0; np < 4; np++) {
            uint32_t b[4];
            ldmx4(wB + np * 2048 + co, b);
            mma_f16(c[2*np],   ah[kk], b[0], b[2]);
            mma_f16(c[2*np+1], ah[kk], b[1], b[3]);
        }
    }
}

__global__ void __launch_bounds__(256, 2)
subgraph_mma_kernel(const float* __restrict__ x,
                    const float* __restrict__ w1g, const float* __restrict__ b1g,
                    const float* __restrict__ lnwg, const float* __restrict__ lnbg,
                    const float* __restrict__ w2g, const float* __restrict__ b2g,
                    float* __restrict__ out) {
    extern __shared__ char sm[];
    const uint32_t smb = smem_u32(sm);
    const int tid = threadIdx.x, wid = tid >> 5, lane = tid & 31;
    const int g = blockIdx.x;

    const float* xg   = x   + (size_t)g * (512 * 64);
    float*       outg = out + (size_t)g * (512 * 128);

    // warm tile 0 into L1 while weights stage
    asm volatile("prefetch.global.L1 [%0];" :: "l"(xg + (size_t)tid * 32));

    // ---- stage weights (fp16, swizzled) + biases ----
    #pragma unroll
    for (int v = 0; v < 2; v++) {
        int lin = tid + v * 256;          // 0..511 : row 0..63, ch 0..7
        int row = lin >> 3, ch = lin & 7;
        const float4* p1 = (const float4*)(w1g + row * 64 + ch * 8);
        const float4* p2 = (const float4*)(w2g + row * 64 + ch * 8);
        conv_store8(sm, OFF_W1, row, ch, p1[0], p1[1]);
        conv_store8(sm, OFF_W2, row, ch, p2[0], p2[1]);
    }
    if (tid < 64) {
        ((float*)(sm + OFF_B1))[tid]  = b1g[tid];
        ((float*)(sm + OFF_B2))[tid]  = b2g[tid];
        ((float*)(sm + OFF_LNW))[tid] = lnwg[tid];
        ((float*)(sm + OFF_LNB))[tid] = lnbg[tid];
    }
    __syncthreads();

    const int r0 = wid * 16;
    const uint32_t lrow  = (uint32_t)((((lane >> 3) & 1) << 3) + (lane & 7)); // 0..15
    const uint32_t lhalf = (uint32_t)(lane >> 4);
    const uint32_t lxor  = (uint32_t)(lane & 7);
    const uint32_t w1B = smb + OFF_W1 + lrow * 128;
    const uint32_t w2B = smb + OFF_W2 + lrow * 128;
    const uint32_t aStg = smb + OFF_AST + wid * 2048 + lrow * 128;

    const int i0 = lane >> 2, m = lane & 3;
    const int lrow16 = lane >> 4;        // coalesced I/O: row sub-index
    const int lcol   = lane & 15;        // coalesced I/O: 16B chunk id
    char* aSt = sm + OFF_AST + wid * 2048;
    char* hSt = sm + OFF_HST + wid * 4096;

    const float2* b1v = (const float2*)(sm + OFF_B1);
    const float2* b2v = (const float2*)(sm + OFF_B2);
    const float2* lw2 = (const float2*)(sm + OFF_LNW);
    const float2* lb2 = (const float2*)(sm + OFF_LNB);

    float rs[32];
    #pragma unroll
    for (int i = 0; i < 32; i++) rs[i] = 0.f;

    // ---- prologue: load + stage tile 0 into A buffer 0 ----
    {
        float4 xp[8];
        #pragma unroll
        for (int u = 0; u < 8; u++) {
            int rowL = u * 2 + lrow16;
            xp[u] = *(const float4*)(xg + (size_t)(r0 + rowL) * 64 + lcol * 4);
        }
        #pragma unroll
        for (int u = 0; u < 8; u++) {
            int rowL = u * 2 + lrow16;
            uint2 hv;
            hv.x = cvt2(xp[u].x, xp[u].y);
            hv.y = cvt2(xp[u].z, xp[u].w);
            *(uint2*)(aSt + rowL * 128 + (((lcol >> 1) ^ (rowL & 7)) << 4) + (lcol & 1) * 8) = hv;
        }
    }
    __syncwarp();

    #pragma unroll 1
    for (int mt = 0; mt < 4; mt++) {
        const uint32_t bufR = (uint32_t)(mt & 1) * ABUF;
        const uint32_t bufW = (uint32_t)((mt + 1) & 1) * ABUF;

        // ---- GEMM1 A fragments via ldmatrix from staged buffer ----
        uint32_t ah[4][4];
        #pragma unroll
        for (int kk = 0; kk < 4; kk++) {
            uint32_t co = ((((uint32_t)(kk << 1) + lhalf) ^ lxor) << 4);
            ldmx4(aStg + bufR + co, ah[kk]);
        }

        // ---- issue next tile's x loads (fly across both GEMMs) ----
        float4 xf[8];
        if (mt < 3) {
            #pragma unroll
            for (int u = 0; u < 8; u++) {
                int rowL = u * 2 + lrow16;
                xf[u] = *(const float4*)(xg + (size_t)((mt + 1) * 128 + r0 + rowL) * 64 + lcol * 4);
            }
        }

        // ---- GEMM1 ----
        float c[8][4];
        #pragma unroll
        for (int i = 0; i < 8; i++)
            #pragma unroll
            for (int j = 0; j < 4; j++) c[i][j] = 0.f;
        gemm64r(ah, w1B, lhalf, lxor, c);

        // ---- bias (in place) + LayerNorm stats ----
        float s0 = 0.f, q0 = 0.f, s1 = 0.f, q1 = 0.f;
        #pragma unroll
        for (int n8 = 0; n8 < 8; n8++) {
            float2 bb = b1v[n8 * 4 + m];
            c[n8][0] += bb.x; c[n8][1] += bb.y;
            c[n8][2] += bb.x; c[n8][3] += bb.y;
            s0 += c[n8][0] + c[n8][1]; q0 += c[n8][0]*c[n8][0] + c[n8][1]*c[n8][1];
            s1 += c[n8][2] + c[n8][3]; q1 += c[n8][2]*c[n8][2] + c[n8][3]*c[n8][3];
        }
        s0 += __shfl_xor_sync(0xffffffffu, s0, 1); s0 += __shfl_xor_sync(0xffffffffu, s0, 2);
        q0 += __shfl_xor_sync(0xffffffffu, q0, 1); q0 += __shfl_xor_sync(0xffffffffu, q0, 2);
        s1 += __shfl_xor_sync(0xffffffffu, s1, 1); s1 += __shfl_xor_sync(0xffffffffu, s1, 2);
        q1 += __shfl_xor_sync(0xffffffffu, q1, 1); q1 += __shfl_xor_sync(0xffffffffu, q1, 2);
        float mu0 = s0 * (1.f/64.f), var0 = q0 * (1.f/64.f) - mu0*mu0;
        float mu1 = s1 * (1.f/64.f), var1 = q1 * (1.f/64.f) - mu1*mu1;
        float inv0 = rsqrtf(var0 + 1e-5f), inv1 = rsqrtf(var1 + 1e-5f);

        // ---- LN*w+b, ReLU -> GEMM2 A fragments (pure registers) ----
        #pragma unroll
        for (int n8 = 0; n8 < 8; n8++) {
            float2 lwv = lw2[n8 * 4 + m], lbv = lb2[n8 * 4 + m];
            float a00 = fmaxf(fmaf((c[n8][0] - mu0) * inv0, lwv.x, lbv.x), 0.f);
            float a01 = fmaxf(fmaf((c[n8][1] - mu0) * inv0, lwv.y, lbv.y), 0.f);
            float a10 = fmaxf(fmaf((c[n8][2] - mu1) * inv1, lwv.x, lbv.x), 0.f);
            float a11 = fmaxf(fmaf((c[n8][3] - mu1) * inv1, lwv.y, lbv.y), 0.f);
            int kk = n8 >> 1, hf = (n8 & 1) * 2;
            ah[kk][hf + 0] = cvt2(a00, a01);
            ah[kk][hf + 1] = cvt2(a10, a11);
        }

        // ---- GEMM2 ----
        #pragma unroll
        for (int i = 0; i < 8; i++)
            #pragma unroll
            for (int j = 0; j < 4; j++) c[i][j] = 0.f;
        gemm64r(ah, w2B, lhalf, lxor, c);

        // ---- stage next tile's A (loads have long landed) ----
        if (mt < 3) {
            #pragma unroll
            for (int u = 0; u < 8; u++) {
                int rowL = u * 2 + lrow16;
                uint2 hv;
                hv.x = cvt2(xf[u].x, xf[u].y);
                hv.y = cvt2(xf[u].z, xf[u].w);
                *(uint2*)(aSt + bufW + rowL * 128
                          + (((lcol >> 1) ^ (rowL & 7)) << 4) + (lcol & 1) * 8) = hv;
            }
        }

        // ---- bias, agent-sum accumulate, stage h into smem ----
        __syncwarp();   // prev h-store reads done before rewriting hSt
        #pragma unroll
        for (int n8 = 0; n8 < 8; n8++) {
            float2 bb = b2v[n8 * 4 + m];
            float v00 = c[n8][0] + bb.x, v01 = c[n8][1] + bb.y;
            float v10 = c[n8][2] + bb.x, v11 = c[n8][3] + bb.y;
            rs[n8*4+0] += v00; rs[n8*4+1] += v01;
            rs[n8*4+2] += v10; rs[n8*4+3] += v11;
            int ch = n8 * 2 + (m >> 1), off8 = (m & 1) * 8;
            int rA = i0, rB = i0 + 8;
            *(float2*)(hSt + rA * 256 + ((ch ^ (rA & 15)) << 4) + off8) = make_float2(v00, v01);
            *(float2*)(hSt + rB * 256 + ((ch ^ (rB & 15)) << 4) + off8) = make_float2(v10, v11);
        }
        __syncwarp();   // hSt + next-A-buf visible warp-wide

        // ---- coalesced h store (full rows, streaming) ----
        #pragma unroll
        for (int u = 0; u < 8; u++) {
            int rowL = u * 2 + lrow16;
            float4 hv = *(const float4*)(hSt + rowL * 256 + ((lcol ^ (rowL & 15)) << 4));
            stcs4(outg + (size_t)(mt * 128 + r0 + rowL) * 128 + 64 + lcol * 4, hv);
        }
    }

    // ---- cross-warp agent-sum reduction (RED aliases h stage) ----
    __syncthreads();
    #pragma unroll
    for (int n8 = 0; n8 < 8; n8++) {
        #pragma unroll
        for (int rr = 0; rr < 2; rr++) {
            int row = r0 + i0 + rr * 8;
            int c16 = n8 * 2 + (m >> 1);
            uint32_t byte = (uint32_t)(row * 256 + ((c16 ^ (row & 15)) << 4) + (m & 1) * 8);
            *(float2*)(sm + OFF_RED + byte) =
                make_float2(rs[n8*4 + rr*2], rs[n8*4 + rr*2 + 1]);
        }
    }
    __syncthreads();

    // ---- fused reduce + broadcast: registers only, 16 streaming stores ----
    #pragma unroll
    for (int v = 0; v < 2; v++) {
        int f = tid + v * 256;
        int t = f >> 4, c16 = f & 15;
        float4 acc = make_float4(0.f, 0.f, 0.f, 0.f);
        #pragma unroll
        for (int a = 0; a < 4; a++) {
            int r = t + a * 32;
            float4 rv = *(const float4*)(sm + OFF_RED + r * 256 + ((c16 ^ (r & 15)) << 4));
            acc.x += rv.x; acc.y += rv.y; acc.z += rv.z; acc.w += rv.w;
        }
        acc.x *= 0.0625f; acc.y *= 0.0625f; acc.z *= 0.0625f; acc.w *= 0.0625f;
        #pragma unroll
        for (int ag = 0; ag < 16; ag++)
            stcs4(outg + (size_t)(ag * 32 + t) * 128 + c16 * 4, acc);
    }
}

extern "C" void kernel_launch(void* const* d_in, const int* in_sizes, int n_in,
                              void* d_out, int out_size) {
    const float* x    = (const float*)d_in[0];
    const float* fc1w = (const float*)d_in[3];
    const float* fc1b = (const float*)d_in[4];
    const float* lnw  = (const float*)d_in[5];
    const float* lnb  = (const float*)d_in[6];
    const float* fc2w = (const float*)d_in[7];
    const float* fc2b = (const float*)d_in[8];
    float* out = (float*)d_out;

    cudaFuncSetAttribute(subgraph_mma_kernel,
                         cudaFuncAttributeMaxDynamicSharedMemorySize, SMEM_TOTAL);
    subgraph_mma_kernel<<<GRPS, 256, SMEM_TOTAL>>>(x, fc1w, fc1b, lnw, lnb, fc2w, fc2b, out);
}

// round 16
// speedup vs baseline: 1.1754x; 1.1754x over previous
#include <cuda_runtime.h>
#include <cuda_fp16.h>
#include <cstdint>

// G=1024 groups (1 CTA each), K=16 agents, T=32, D=64.
// out[n,t,0:64]=group mean of h ; out[n,t,64:128]=h ; h=fc2(relu(LN(fc1(x))))
// mma.sync m16n8k16 fp16 single-term; warp-private smem staging for coalesced
// x loads and h stores; fused register-resident mean broadcast epilogue.
// R16: R12 skeleton + __ldg (LDG.E.CI) on all read-only global loads.
#define GRPS 1024

// smem byte offsets
#define OFF_W1  0          // 64 rows x 128B fp16, swizzled
#define OFF_W2  8192
#define OFF_AST 16384      // A stage: 8 warps x 16 rows x 128B fp16 = 16KB
#define OFF_HST 32768      // h stage: 8 warps x 16 rows x 256B f32 = 32KB
#define OFF_B1  65536
#define OFF_B2  65792
#define OFF_LNW 66048
#define OFF_LNB 66304
#define SMEM_TOTAL 66560
// post-loop alias:
#define OFF_RED   OFF_HST  // [128 rows][64 cols] f32, 256B rows, chunk-swizzled

__device__ __forceinline__ uint32_t smem_u32(const void* p) {
    uint32_t a;
    asm("{ .reg .u64 t; cvta.to.shared.u64 t, %1; cvt.u32.u64 %0, t; }" : "=r"(a) : "l"(p));
    return a;
}
__device__ __forceinline__ void ldmx4(uint32_t addr, uint32_t* r) {
    asm volatile("ldmatrix.sync.aligned.m8n8.x4.shared.b16 {%0,%1,%2,%3}, [%4];"
                 : "=r"(r[0]), "=r"(r[1]), "=r"(r[2]), "=r"(r[3]) : "r"(addr));
}
__device__ __forceinline__ void mma_f16(float* c, const uint32_t* a,
                                        uint32_t b0, uint32_t b1) {
    asm volatile(
        "mma.sync.aligned.m16n8k16.row.col.f32.f16.f16.f32 "
        "{%0,%1,%2,%3}, {%4,%5,%6,%7}, {%8,%9}, {%0,%1,%2,%3};"
        : "+f"(c[0]), "+f"(c[1]), "+f"(c[2]), "+f"(c[3])
        : "r"(a[0]), "r"(a[1]), "r"(a[2]), "r"(a[3]), "r"(b0), "r"(b1));
}
__device__ __forceinline__ uint32_t cvt2(float x0, float x1) {
    __half2 h = __floats2half2_rn(x0, x1);
    return *(uint32_t*)&h;
}
__device__ __forceinline__ void stcs4(float* p, float4 v) {
    asm volatile("st.global.cs.v4.f32 [%0], {%1,%2,%3,%4};"
                 :: "l"(p), "f"(v.x), "f"(v.y), "f"(v.z), "f"(v.w) : "memory");
}
// convert 8 consecutive fp32 -> one 16B fp16 chunk, swizzled store (weights)
__device__ __forceinline__ void conv_store8(char* sm, int off, int row, int ch,
                                            float4 a, float4 b) {
    uint4 v;
    v.x = cvt2(a.x, a.y); v.y = cvt2(a.z, a.w);
    v.z = cvt2(b.x, b.y); v.w = cvt2(b.z, b.w);
    int bo = row * 128 + ((ch ^ (row & 7)) << 4);
    *(uint4*)(sm + off + bo) = v;
}

// 16x64 stripe GEMM vs 64x64 fp16 weights, register A (single term).
__device__ __forceinline__ void gemm64r(const uint32_t ah[4][4],
                                        uint32_t wB,
                                        uint32_t lhalf, uint32_t lxor,
                                        float c[8][4]) {
    #pragma unroll
    for (int kk = 0; kk < 4; kk++) {
        uint32_t co = ((((uint32_t)(kk << 1) + lhalf) ^ lxor) << 4);
        #pragma unroll
        for (int np = 0; np < 4; np++) {
            uint32_t b[4];
            ldmx4(wB + np * 2048 + co, b);
            mma_f16(c[2*np],   ah[kk], b[0], b[2]);
            mma_f16(c[2*np+1], ah[kk], b[1], b[3]);
        }
    }
}

__global__ void __launch_bounds__(256, 2)
subgraph_mma_kernel(const float* __restrict__ x,
                    const float* __restrict__ w1g, const float* __restrict__ b1g,
                    const float* __restrict__ lnwg, const float* __restrict__ lnbg,
                    const float* __restrict__ w2g, const float* __restrict__ b2g,
                    float* __restrict__ out) {
    extern __shared__ char sm[];
    const uint32_t smb = smem_u32(sm);
    const int tid = threadIdx.x, wid = tid >> 5, lane = tid & 31;
    const int g = blockIdx.x;

    const float* xg   = x   + (size_t)g * (512 * 64);
    float*       outg = out + (size_t)g * (512 * 128);

    // warm tile 0 into L1 while weights stage
    asm volatile("prefetch.global.L1 [%0];" :: "l"(xg + (size_t)tid * 32));

    // ---- stage weights (fp16, swizzled) + biases ----
    #pragma unroll
    for (int v = 0; v < 2; v++) {
        int lin = tid + v * 256;          // 0..511 : row 0..63, ch 0..7
        int row = lin >> 3, ch = lin & 7;
        float4 w1a = __ldg((const float4*)(w1g + row * 64 + ch * 8));
        float4 w1b = __ldg((const float4*)(w1g + row * 64 + ch * 8 + 4));
        float4 w2a = __ldg((const float4*)(w2g + row * 64 + ch * 8));
        float4 w2b = __ldg((const float4*)(w2g + row * 64 + ch * 8 + 4));
        conv_store8(sm, OFF_W1, row, ch, w1a, w1b);
        conv_store8(sm, OFF_W2, row, ch, w2a, w2b);
    }
    if (tid < 64) {
        ((float*)(sm + OFF_B1))[tid]  = __ldg(b1g + tid);
        ((float*)(sm + OFF_B2))[tid]  = __ldg(b2g + tid);
        ((float*)(sm + OFF_LNW))[tid] = __ldg(lnwg + tid);
        ((float*)(sm + OFF_LNB))[tid] = __ldg(lnbg + tid);
    }
    __syncthreads();

    const int r0 = wid * 16;
    const uint32_t lrow  = (uint32_t)((((lane >> 3) & 1) << 3) + (lane & 7)); // 0..15
    const uint32_t lhalf = (uint32_t)(lane >> 4);
    const uint32_t lxor  = (uint32_t)(lane & 7);
    const uint32_t w1B = smb + OFF_W1 + lrow * 128;
    const uint32_t w2B = smb + OFF_W2 + lrow * 128;
    const uint32_t aStg = smb + OFF_AST + wid * 2048 + lrow * 128;

    const int i0 = lane >> 2, m = lane & 3;
    const int lrow16 = lane >> 4;        // coalesced I/O: row sub-index
    const int lcol   = lane & 15;        // coalesced I/O: 16B chunk id
    char* aSt = sm + OFF_AST + wid * 2048;
    char* hSt = sm + OFF_HST + wid * 4096;

    const float2* b1v = (const float2*)(sm + OFF_B1);
    const float2* b2v = (const float2*)(sm + OFF_B2);
    const float2* lw2 = (const float2*)(sm + OFF_LNW);
    const float2* lb2 = (const float2*)(sm + OFF_LNB);

    float rs[32];
    #pragma unroll
    for (int i = 0; i < 32; i++) rs[i] = 0.f;

    #pragma unroll 1
    for (int mt = 0; mt < 4; mt++) {
        __syncwarp();    // stage buffers free (prev tile's ldmx/LDS complete)

        // ---- coalesced x load (full rows, LDG.CI) -> fp16 -> A stage ----
        float4 xf[8];
        #pragma unroll
        for (int u = 0; u < 8; u++) {
            int rowL = u * 2 + lrow16;
            xf[u] = __ldg((const float4*)(xg + (size_t)(mt * 128 + r0 + rowL) * 64 + lcol * 4));
        }
        if (mt < 3)
            asm volatile("prefetch.global.L1 [%0];"
                         :: "l"(xg + (size_t)(mt + 1) * 128 * 64 + (size_t)tid * 32));
        #pragma unroll
        for (int u = 0; u < 8; u++) {
            int rowL = u * 2 + lrow16;
            uint2 hv;
            hv.x = cvt2(xf[u].x, xf[u].y);
            hv.y = cvt2(xf[u].z, xf[u].w);
            *(uint2*)(aSt + rowL * 128 + (((lcol >> 1) ^ (rowL & 7)) << 4) + (lcol & 1) * 8) = hv;
        }
        __syncwarp();

        // ---- GEMM1 A fragments via ldmatrix from A stage ----
        uint32_t ah[4][4];
        #pragma unroll
        for (int kk = 0; kk < 4; kk++) {
            uint32_t co = ((((uint32_t)(kk << 1) + lhalf) ^ lxor) << 4);
            ldmx4(aStg + co, ah[kk]);
        }

        // ---- GEMM1 ----
        float c[8][4];
        #pragma unroll
        for (int i = 0; i < 8; i++)
            #pragma unroll
            for (int j = 0; j < 4; j++) c[i][j] = 0.f;
        gemm64r(ah, w1B, lhalf, lxor, c);

        // ---- bias (in place) + LayerNorm stats ----
        float s0 = 0.f, q0 = 0.f, s1 = 0.f, q1 = 0.f;
        #pragma unroll
        for (int n8 = 0; n8 < 8; n8++) {
            float2 bb = b1v[n8 * 4 + m];
            c[n8][0] += bb.x; c[n8][1] += bb.y;
            c[n8][2] += bb.x; c[n8][3] += bb.y;
            s0 += c[n8][0] + c[n8][1]; q0 += c[n8][0]*c[n8][0] + c[n8][1]*c[n8][1];
            s1 += c[n8][2] + c[n8][3]; q1 += c[n8][2]*c[n8][2] + c[n8][3]*c[n8][3];
        }
        s0 += __shfl_xor_sync(0xffffffffu, s0, 1); s0 += __shfl_xor_sync(0xffffffffu, s0, 2);
        q0 += __shfl_xor_sync(0xffffffffu, q0, 1); q0 += __shfl_xor_sync(0xffffffffu, q0, 2);
        s1 += __shfl_xor_sync(0xffffffffu, s1, 1); s1 += __shfl_xor_sync(0xffffffffu, s1, 2);
        q1 += __shfl_xor_sync(0xffffffffu, q1, 1); q1 += __shfl_xor_sync(0xffffffffu, q1, 2);
        float mu0 = s0 * (1.f/64.f), var0 = q0 * (1.f/64.f) - mu0*mu0;
        float mu1 = s1 * (1.f/64.f), var1 = q1 * (1.f/64.f) - mu1*mu1;
        float inv0 = rsqrtf(var0 + 1e-5f), inv1 = rsqrtf(var1 + 1e-5f);

        // ---- LN*w+b, ReLU -> GEMM2 A fragments (pure registers) ----
        #pragma unroll
        for (int n8 = 0; n8 < 8; n8++) {
            float2 lwv = lw2[n8 * 4 + m], lbv = lb2[n8 * 4 + m];
            float a00 = fmaxf(fmaf((c[n8][0] - mu0) * inv0, lwv.x, lbv.x), 0.f);
            float a01 = fmaxf(fmaf((c[n8][1] - mu0) * inv0, lwv.y, lbv.y), 0.f);
            float a10 = fmaxf(fmaf((c[n8][2] - mu1) * inv1, lwv.x, lbv.x), 0.f);
            float a11 = fmaxf(fmaf((c[n8][3] - mu1) * inv1, lwv.y, lbv.y), 0.f);
            int kk = n8 >> 1, hf = (n8 & 1) * 2;
            ah[kk][hf + 0] = cvt2(a00, a01);
            ah[kk][hf + 1] = cvt2(a10, a11);
        }

        // ---- GEMM2 ----
        #pragma unroll
        for (int i = 0; i < 8; i++)
            #pragma unroll
            for (int j = 0; j < 4; j++) c[i][j] = 0.f;
        gemm64r(ah, w2B, lhalf, lxor, c);

        // ---- bias, agent-sum accumulate, stage h into smem ----
        #pragma unroll
        for (int n8 = 0; n8 < 8; n8++) {
            float2 bb = b2v[n8 * 4 + m];
            float v00 = c[n8][0] + bb.x, v01 = c[n8][1] + bb.y;
            float v10 = c[n8][2] + bb.x, v11 = c[n8][3] + bb.y;
            rs[n8*4+0] += v00; rs[n8*4+1] += v01;
            rs[n8*4+2] += v10; rs[n8*4+3] += v11;
            int ch = n8 * 2 + (m >> 1), off8 = (m & 1) * 8;
            int rA = i0, rB = i0 + 8;
            *(float2*)(hSt + rA * 256 + ((ch ^ (rA & 15)) << 4) + off8) = make_float2(v00, v01);
            *(float2*)(hSt + rB * 256 + ((ch ^ (rB & 15)) << 4) + off8) = make_float2(v10, v11);
        }
        __syncwarp();

        // ---- coalesced h store (full rows, streaming) ----
        #pragma unroll
        for (int u = 0; u < 8; u++) {
            int rowL = u * 2 + lrow16;
            float4 hv = *(const float4*)(hSt + rowL * 256 + ((lcol ^ (rowL & 15)) << 4));
            stcs4(outg + (size_t)(mt * 128 + r0 + rowL) * 128 + 64 + lcol * 4, hv);
        }
    }

    // ---- cross-warp agent-sum reduction (RED aliases h stage) ----
    __syncthreads();
    #pragma unroll
    for (int n8 = 0; n8 < 8; n8++) {
        #pragma unroll
        for (int rr = 0; rr < 2; rr++) {
            int row = r0 + i0 + rr * 8;
            int c16 = n8 * 2 + (m >> 1);
            uint32_t byte = (uint32_t)(row * 256 + ((c16 ^ (row & 15)) << 4) + (m & 1) * 8);
            *(float2*)(sm + OFF_RED + byte) =
                make_float2(rs[n8*4 + rr*2], rs[n8*4 + rr*2 + 1]);
        }
    }
    __syncthreads();

    // ---- fused reduce + broadcast: registers only, 16 streaming stores ----
    #pragma unroll
    for (int v = 0; v < 2; v++) {
        int f = tid + v * 256;
        int t = f >> 4, c16 = f & 15;
        float4 acc = make_float4(0.f, 0.f, 0.f, 0.f);
        #pragma unroll
        for (int a = 0; a < 4; a++) {
            int r = t + a * 32;
            float4 rv = *(const float4*)(sm + OFF_RED + r * 256 + ((c16 ^ (r & 15)) << 4));
            acc.x += rv.x; acc.y += rv.y; acc.z += rv.z; acc.w += rv.w;
        }
        acc.x *= 0.0625f; acc.y *= 0.0625f; acc.z *= 0.0625f; acc.w *= 0.0625f;
        #pragma unroll
        for (int ag = 0; ag < 16; ag++)
            stcs4(outg + (size_t)(ag * 32 + t) * 128 + c16 * 4, acc);
    }
}

extern "C" void kernel_launch(void* const* d_in, const int* in_sizes, int n_in,
                              void* d_out, int out_size) {
    const float* x    = (const float*)d_in[0];
    const float* fc1w = (const float*)d_in[3];
    const float* fc1b = (const float*)d_in[4];
    const float* lnw  = (const float*)d_in[5];
    const float* lnb  = (const float*)d_in[6];
    const float* fc2w = (const float*)d_in[7];
    const float* fc2b = (const float*)d_in[8];
    float* out = (float*)d_out;

    cudaFuncSetAttribute(subgraph_mma_kernel,
                         cudaFuncAttributeMaxDynamicSharedMemorySize, SMEM_TOTAL);
    subgraph_mma_kernel<<<GRPS, 256, SMEM_TOTAL>>>(x, fc1w, fc1b, lnw, lnb, fc2w, fc2b, out);
}